// round 2
// baseline (speedup 1.0000x reference)
#include <cuda_runtime.h>
#include <cuda_bf16.h>
#include <cstdint>
#include <cstddef>

// ============================================================================
// Problem shapes (fixed):
//   x        [4,2048,4096] -> M=8192, K1=4096
//   base_w   [4096,4096]   -> N=4096
//   base_b   [4096]
//   A        [64,4096]     (reservoir)
//   B        [16,4096,64]  (per-expert low-rank)
//   router_w [16,4096]
//   out      [8192,4096] f32
//
// Folded formulation:
//   HL  = x @ WS^T            WS = [A ; router_w ; 0] (128 x 4096)
//   h   = HL[:, 0:64], logits = HL[:, 64:80]
//   U[t, e*64+r] = combine[t,e] * h[t,r]          (8192 x 1024)
//   W2B[o, e*64+r] = 0.5 * B[e,o,r]               (4096 x 1024)
//   out = x @ base_w^T + U @ W2B^T + bias         (single GEMM, K=5120)
// ============================================================================

#define M_TOK   8192
#define N_OUT   4096
#define K_IN    4096
#define K_LORA  1024
#define NEXP    16
#define RANK    64

#define BM 128
#define BN 128
#define BK 32
#define NTHREADS 256
#define SSTRIDE 36          // smem row stride in floats (32 + 4 pad)
#define SMEM_FLOATS (4 * BM * SSTRIDE)   // 2 stages A + 2 stages B (BM==BN)
#define SMEM_BYTES (SMEM_FLOATS * 4)

// -------- scratch (device globals; no allocation allowed) --------
__device__ float g_WS[128 * K_IN];            // 2 MB
__device__ float g_HL[M_TOK * 128];           // 4 MB
__device__ float g_U[M_TOK * K_LORA];         // 32 MB
__device__ float g_W2B[N_OUT * K_LORA];       // 16 MB

// ---------------- PTX helpers ----------------
__device__ __forceinline__ uint32_t smem_u32(const void* p) {
    uint32_t a;
    asm("{ .reg .u64 t; cvta.to.shared.u64 t, %1; cvt.u32.u64 %0, t; }" : "=r"(a) : "l"(p));
    return a;
}

__device__ __forceinline__ uint32_t f2tf32(float f) {
    uint32_t u;
    asm("cvt.rna.tf32.f32 %0, %1;" : "=r"(u) : "f"(f));
    return u;
}

#define CP_ASYNC16(dst_u32, src_ptr) \
    asm volatile("cp.async.cg.shared.global [%0], [%1], 16;" :: "r"(dst_u32), "l"(src_ptr) : "memory")
#define CP_COMMIT() asm volatile("cp.async.commit_group;" ::: "memory")
#define CP_WAIT0()  asm volatile("cp.async.wait_group 0;" ::: "memory")

__device__ __forceinline__ void mma_tf32(float c[4],
                                         uint32_t a0, uint32_t a1, uint32_t a2, uint32_t a3,
                                         uint32_t b0, uint32_t b1) {
    asm volatile(
        "mma.sync.aligned.m16n8k8.row.col.f32.tf32.tf32.f32 "
        "{%0,%1,%2,%3}, {%4,%5,%6,%7}, {%8,%9}, {%0,%1,%2,%3};"
        : "+f"(c[0]), "+f"(c[1]), "+f"(c[2]), "+f"(c[3])
        : "r"(a0), "r"(a1), "r"(a2), "r"(a3), "r"(b0), "r"(b1));
}

// ============================================================================
// Generic two-segment NT GEMM:  C[M,N] = A1@B1^T (kt1 tiles) + A2@B2^T (kt2) + bias
// A row-major [M, lda], B row-major [N, ldb] (i.e. weights with K contiguous).
// Grid: (N/BN, M/BM). 256 threads, warp grid 2x4, warp tile 64x32.
// ============================================================================
__global__ __launch_bounds__(NTHREADS, 2)
void gemm_tf32(const float* __restrict__ A1, const float* __restrict__ B1,
               int lda1, int ldb1, int kt1,
               const float* __restrict__ A2, const float* __restrict__ B2,
               int lda2, int ldb2, int kt2,
               const float* __restrict__ bias,
               float* __restrict__ C, int ldc)
{
    extern __shared__ float smem[];
    float* As = smem;                            // 2 stages of BM x SSTRIDE
    float* Bs = smem + 2 * BM * SSTRIDE;         // 2 stages of BN x SSTRIDE

    const int tid = threadIdx.x;
    const int ldrow = tid >> 3;                  // 0..31
    const int ldcol = (tid & 7) * 4;             // 0,4,...,28

    const int rowA_base = blockIdx.y * BM;
    const int rowB_base = blockIdx.x * BN;

    const uint32_t sA0 = smem_u32(As);
    const uint32_t sB0 = smem_u32(Bs);

    const int KT = kt1 + kt2;

    // ---- async tile loader ----
    auto load_tile = [&](int stage, int kt) {
        const float *Ap, *Bp;
        int la, lb, klocal;
        if (kt < kt1) { Ap = A1; Bp = B1; la = lda1; lb = ldb1; klocal = kt * BK; }
        else          { Ap = A2; Bp = B2; la = lda2; lb = ldb2; klocal = (kt - kt1) * BK; }
        const uint32_t sa = sA0 + (uint32_t)stage * BM * SSTRIDE * 4;
        const uint32_t sb = sB0 + (uint32_t)stage * BM * SSTRIDE * 4;
        #pragma unroll
        for (int i = 0; i < 4; i++) {
            const int r = ldrow + i * 32;
            const float* srcA = Ap + (size_t)(rowA_base + r) * la + klocal + ldcol;
            CP_ASYNC16(sa + (uint32_t)(r * SSTRIDE + ldcol) * 4, srcA);
            const float* srcB = Bp + (size_t)(rowB_base + r) * lb + klocal + ldcol;
            CP_ASYNC16(sb + (uint32_t)(r * SSTRIDE + ldcol) * 4, srcB);
        }
    };

    const int warp = tid >> 5;
    const int lane = tid & 31;
    const int wm = warp >> 2;        // 0..1
    const int wn = warp & 3;         // 0..3
    const int g  = lane >> 2;        // 0..7
    const int t4 = lane & 3;         // 0..3

    float acc[4][4][4];
    #pragma unroll
    for (int i = 0; i < 4; i++)
        #pragma unroll
        for (int j = 0; j < 4; j++)
            #pragma unroll
            for (int v = 0; v < 4; v++) acc[i][j][v] = 0.0f;

    load_tile(0, 0);
    CP_COMMIT();

    for (int kt = 0; kt < KT; ++kt) {
        CP_WAIT0();
        __syncthreads();
        if (kt + 1 < KT) { load_tile((kt + 1) & 1, kt + 1); CP_COMMIT(); }

        const float* as = As + (kt & 1) * BM * SSTRIDE;
        const float* bs = Bs + (kt & 1) * BM * SSTRIDE;

        #pragma unroll
        for (int k0 = 0; k0 < BK; k0 += 8) {
            uint32_t af[4][4];
            #pragma unroll
            for (int mt = 0; mt < 4; mt++) {
                const int m = wm * 64 + mt * 16 + g;
                af[mt][0] = f2tf32(as[m * SSTRIDE + k0 + t4]);
                af[mt][1] = f2tf32(as[(m + 8) * SSTRIDE + k0 + t4]);
                af[mt][2] = f2tf32(as[m * SSTRIDE + k0 + t4 + 4]);
                af[mt][3] = f2tf32(as[(m + 8) * SSTRIDE + k0 + t4 + 4]);
            }
            uint32_t bf[4][2];
            #pragma unroll
            for (int nt = 0; nt < 4; nt++) {
                const int n = wn * 32 + nt * 8 + g;
                bf[nt][0] = f2tf32(bs[n * SSTRIDE + k0 + t4]);
                bf[nt][1] = f2tf32(bs[n * SSTRIDE + k0 + t4 + 4]);
            }
            #pragma unroll
            for (int mt = 0; mt < 4; mt++)
                #pragma unroll
                for (int nt = 0; nt < 4; nt++)
                    mma_tf32(acc[mt][nt], af[mt][0], af[mt][1], af[mt][2], af[mt][3],
                             bf[nt][0], bf[nt][1]);
        }
        __syncthreads();
    }

    // ---- epilogue ----
    #pragma unroll
    for (int mt = 0; mt < 4; mt++) {
        const int row = rowA_base + wm * 64 + mt * 16 + g;
        #pragma unroll
        for (int nt = 0; nt < 4; nt++) {
            const int col = rowB_base + wn * 32 + nt * 8 + t4 * 2;
            float b0 = 0.0f, b1 = 0.0f;
            if (bias) { b0 = __ldg(bias + col); b1 = __ldg(bias + col + 1); }
            float2 v0, v1;
            v0.x = acc[mt][nt][0] + b0; v0.y = acc[mt][nt][1] + b1;
            v1.x = acc[mt][nt][2] + b0; v1.y = acc[mt][nt][3] + b1;
            *reinterpret_cast<float2*>(C + (size_t)row * ldc + col) = v0;
            *reinterpret_cast<float2*>(C + (size_t)(row + 8) * ldc + col) = v1;
        }
    }
}

// ============================================================================
// Pack WS = [A (64 rows); router_w (16 rows); zeros] -> [128, 4096]
// ============================================================================
__global__ void pack_ws(float* __restrict__ WS, const float* __restrict__ A,
                        const float* __restrict__ RW)
{
    int i = blockIdx.x * blockDim.x + threadIdx.x;
    if (i >= 128 * K_IN) return;
    int row = i >> 12;                 // /4096
    float v = 0.0f;
    if (row < 64) v = A[i];
    else if (row < 80) v = RW[i - 64 * K_IN];
    WS[i] = v;
}

// ============================================================================
// Pack W2B[o, e*64+r] = 0.5 * B[e, o, r]   (SCALING = 32/64 folded here)
// ============================================================================
__global__ void pack_w2b(float* __restrict__ W2B, const float* __restrict__ B)
{
    int i = blockIdx.x * blockDim.x + threadIdx.x;
    if (i >= N_OUT * K_LORA) return;
    int o = i >> 10;                   // /1024
    int c = i & 1023;
    int e = c >> 6;
    int r = c & 63;
    W2B[i] = 0.5f * B[((size_t)e << 18) + ((size_t)o << 6) + r];
}

// ============================================================================
// Routing: one warp per token. softmax over 16 logits, top-2, renormalize,
// build U row: U[t, e*64+r] = w_e * h[t,r] (selected experts), 0 elsewhere.
// ============================================================================
__global__ void routing_kernel(float* __restrict__ U, const float* __restrict__ HL)
{
    const int wid = (blockIdx.x * blockDim.x + threadIdx.x) >> 5;
    const int lane = threadIdx.x & 31;
    if (wid >= M_TOK) return;

    const float* hl = HL + (size_t)wid * 128;

    float logit = (lane < NEXP) ? hl[64 + lane] : -1e30f;
    float mx = logit;
    #pragma unroll
    for (int o = 16; o > 0; o >>= 1) mx = fmaxf(mx, __shfl_xor_sync(0xffffffffu, mx, o));
    float p = (lane < NEXP) ? __expf(logit - mx) : 0.0f;
    float s = p;
    #pragma unroll
    for (int o = 16; o > 0; o >>= 1) s += __shfl_xor_sync(0xffffffffu, s, o);
    const float prob = p / s;

    // top-1 (larger prob; ties -> lower index, matching top_k)
    float v1 = prob; int i1 = (lane < NEXP) ? lane : 1000;
    #pragma unroll
    for (int o = 16; o > 0; o >>= 1) {
        float vo = __shfl_xor_sync(0xffffffffu, v1, o);
        int io = __shfl_xor_sync(0xffffffffu, i1, o);
        if (vo > v1 || (vo == v1 && io < i1)) { v1 = vo; i1 = io; }
    }
    // top-2
    float v2 = (lane == i1) ? -1.0f : prob;
    int i2 = (lane < NEXP && lane != i1) ? lane : 1000;
    #pragma unroll
    for (int o = 16; o > 0; o >>= 1) {
        float vo = __shfl_xor_sync(0xffffffffu, v2, o);
        int io = __shfl_xor_sync(0xffffffffu, i2, o);
        if (vo > v2 || (vo == v2 && io < i2)) { v2 = vo; i2 = io; }
    }

    const float rn = 1.0f / (v1 + v2 + 1e-6f);
    const float w1 = v1 * rn;
    const float w2 = v2 * rn;

    // h[r]: lane holds r=lane and r=lane+32
    const float h0 = hl[lane];
    const float h1 = hl[lane + 32];

    float* urow = U + (size_t)wid * K_LORA;
    // column c = j*32 + lane : expert e = j>>1, r = lane + (j&1)*32
    #pragma unroll
    for (int j = 0; j < 32; j++) {
        const int e = j >> 1;
        const float w = (e == i1) ? w1 : ((e == i2) ? w2 : 0.0f);
        const float hv = (j & 1) ? h1 : h0;
        urow[j * 32 + lane] = w * hv;
    }
}

// ============================================================================
// Launch
// ============================================================================
extern "C" void kernel_launch(void* const* d_in, const int* in_sizes, int n_in,
                              void* d_out, int out_size)
{
    const float* x      = (const float*)d_in[0];
    const float* base_w = (const float*)d_in[1];
    const float* base_b = (const float*)d_in[2];
    const float* A      = (const float*)d_in[3];
    const float* B      = (const float*)d_in[4];
    const float* rw     = (const float*)d_in[5];
    float* out = (float*)d_out;

    float *ws = nullptr, *hl = nullptr, *u = nullptr, *w2b = nullptr;
    cudaGetSymbolAddress((void**)&ws,  g_WS);
    cudaGetSymbolAddress((void**)&hl,  g_HL);
    cudaGetSymbolAddress((void**)&u,   g_U);
    cudaGetSymbolAddress((void**)&w2b, g_W2B);

    cudaFuncSetAttribute(gemm_tf32, cudaFuncAttributeMaxDynamicSharedMemorySize, SMEM_BYTES);

    // pack weights
    pack_ws <<<(128 * K_IN + 255) / 256, 256>>>(ws, A, rw);
    pack_w2b<<<(N_OUT * K_LORA + 255) / 256, 256>>>(w2b, B);

    // HL = x @ WS^T   (M=8192, N=128, K=4096)
    {
        dim3 grid(1, M_TOK / BM);
        gemm_tf32<<<grid, NTHREADS, SMEM_BYTES>>>(
            x, ws, K_IN, K_IN, K_IN / BK,
            nullptr, nullptr, 0, 0, 0,
            nullptr, hl, 128);
    }

    // routing + U build (one warp per token)
    routing_kernel<<<M_TOK / 8, 256>>>(u, hl);

    // out = x @ base_w^T + U @ W2B^T + bias   (M=8192, N=4096, K=4096+1024)
    {
        dim3 grid(N_OUT / BN, M_TOK / BM);
        gemm_tf32<<<grid, NTHREADS, SMEM_BYTES>>>(
            x, base_w, K_IN, K_IN, K_IN / BK,
            u, w2b, K_LORA, K_LORA, K_LORA / BK,
            base_b, out, N_OUT);
    }
}

// round 5
// speedup vs baseline: 1.1255x; 1.1255x over previous
#include <cuda_runtime.h>
#include <cstdint>
#include <cstddef>

// ============================================================================
// ResMoELoRALinear, folded:
//   HL  = Xr @ WS^T                      (M=8192, N=128, K=4096)
//   U[t, e*64+r] = combine[t,e]*h[t,r]
//   out = Xr @ Wr^T + U @ W2B^T + bias   (M=8192, N=4096, K=4096+1024)
// All GEMM operands pre-rounded to tf32 (RNA) AND K-permuted within each
// aligned 16-block by p(k) = (k&3)*4 + (k>>2)  (4x4 transpose, involution,
// applied to BOTH sides of every dot product -> results unchanged).
// This makes each mma fragment a contiguous float4 in shared memory.
// ============================================================================

#define M_TOK  8192
#define N_OUT  4096
#define K_IN   4096
#define K_LORA 1024
#define NEXP   16

#define BM     128
#define BN     128
#define BK     32
#define STAGES 3
#define NTH    256

#define ABYTES (BM * BK * 4)          // 16384
#define BBYTES (BN * BK * 4)          // 16384
#define STAGEB (ABYTES + BBYTES)      // 32768
#define SMEM_BYTES (STAGES * STAGEB)  // 98304

// -------- scratch (device globals; no allocation allowed) --------
__device__ float g_Xr[(size_t)M_TOK * K_IN];
__device__ float g_Wr[(size_t)N_OUT * K_IN];
__device__ float g_WS[128 * K_IN];
__device__ float g_HL[M_TOK * 128];
__device__ float g_U[(size_t)M_TOK * K_LORA];
__device__ float g_W2B[(size_t)N_OUT * K_LORA];

// ---------------- helpers ----------------
__device__ __forceinline__ uint32_t smem_u32(const void* p) {
    uint32_t a;
    asm("{ .reg .u64 t; cvta.to.shared.u64 t, %1; cvt.u32.u64 %0, t; }" : "=r"(a) : "l"(p));
    return a;
}
__device__ __forceinline__ float rnaf(float f) {
    uint32_t u;
    asm("cvt.rna.tf32.f32 %0, %1;" : "=r"(u) : "f"(f));
    return __uint_as_float(u);
}
// K permutation within aligned 16-block (involution)
__device__ __forceinline__ int kperm(int i) {
    return (i & ~15) | ((i & 3) << 2) | ((i >> 2) & 3);
}

#define CP_ASYNC16(dst_u32, src_ptr) \
    asm volatile("cp.async.cg.shared.global [%0], [%1], 16;" :: "r"(dst_u32), "l"(src_ptr) : "memory")
#define CP_COMMIT() asm volatile("cp.async.commit_group;" ::: "memory")
#define CP_WAIT1()  asm volatile("cp.async.wait_group 1;" ::: "memory")
#define CP_WAIT0()  asm volatile("cp.async.wait_group 0;" ::: "memory")

#define LDS128(r0, r1, r2, r3, addr) \
    asm volatile("ld.shared.v4.b32 {%0,%1,%2,%3}, [%4];" \
        : "=r"(r0), "=r"(r1), "=r"(r2), "=r"(r3) : "r"(addr))

__device__ __forceinline__ void mma_tf32(float c[4],
                                         uint32_t a0, uint32_t a1, uint32_t a2, uint32_t a3,
                                         uint32_t b0, uint32_t b1) {
    asm volatile(
        "mma.sync.aligned.m16n8k8.row.col.f32.tf32.tf32.f32 "
        "{%0,%1,%2,%3}, {%4,%5,%6,%7}, {%8,%9}, {%0,%1,%2,%3};"
        : "+f"(c[0]), "+f"(c[1]), "+f"(c[2]), "+f"(c[3])
        : "r"(a0), "r"(a1), "r"(a2), "r"(a3), "r"(b0), "r"(b1));
}

// smem chunk swizzle: 16B chunk c of row r stored at slot c ^ sigma(r&7)
__device__ __forceinline__ int sigma(int g) { return ((g & 1) << 2) | (g >> 1); }

// ============================================================================
// Two-segment NT GEMM: C = A1@B1^T (kt1 k-tiles) + A2@B2^T (kt2) + bias
// 256 threads, warp grid 2(m) x 4(n), warp tile 64x32.
// Operands are pre-rounded tf32 bits in kperm'd layout.
// ============================================================================
__global__ __launch_bounds__(NTH, 2)
void gemm_tf32(const float* __restrict__ A1, const float* __restrict__ B1,
               int lda1, int ldb1, int kt1,
               const float* __restrict__ A2, const float* __restrict__ B2,
               int lda2, int ldb2, int kt2,
               const float* __restrict__ bias,
               float* __restrict__ C, int ldc)
{
    extern __shared__ char smem[];
    const uint32_t sbase = smem_u32(smem);

    const int tid  = threadIdx.x;
    const int warp = tid >> 5;
    const int lane = tid & 31;
    const int wm = warp >> 2;          // 0..1  (64 rows)
    const int wn = warp & 3;           // 0..3  (32 cols)
    const int g  = lane >> 2;          // 0..7
    const int t4 = lane & 3;           // 0..3
    const int sg = sigma(g);

    const int rowAb = blockIdx.y * BM;
    const int rowBb = blockIdx.x * BN;
    const int KT = kt1 + kt2;

    // ---- stage loader: 2048 16B chunks / 256 threads = 8 each ----
    const int ldr = tid >> 3;          // 0..31 within quarter... (row id per 8-thread grp)
    const int ldc4 = tid & 7;          // chunk 0..7
    auto load_stage = [&](int st, int kt) {
        const float *Ap, *Bp;
        int la, lb, kb;
        if (kt < kt1) { Ap = A1; Bp = B1; la = lda1; lb = ldb1; kb = kt * BK; }
        else          { Ap = A2; Bp = B2; la = lda2; lb = ldb2; kb = (kt - kt1) * BK; }
        const uint32_t ab = sbase + (uint32_t)st * STAGEB;
        const uint32_t bb = ab + ABYTES;
        #pragma unroll
        for (int i = 0; i < 4; i++) {
            const int r = ldr + i * 32;                       // 0..127 A rows
            const int slot = ldc4 ^ sigma(r & 7);
            const float* srcA = Ap + (size_t)(rowAb + r) * la + kb + ldc4 * 4;
            CP_ASYNC16(ab + (uint32_t)(r * 128 + slot * 16), srcA);
            const float* srcB = Bp + (size_t)(rowBb + r) * lb + kb + ldc4 * 4;
            CP_ASYNC16(bb + (uint32_t)(r * 128 + slot * 16), srcB);
        }
        CP_COMMIT();
    };

    float acc[4][4][4];
    #pragma unroll
    for (int i = 0; i < 4; i++)
        #pragma unroll
        for (int j = 0; j < 4; j++)
            #pragma unroll
            for (int v = 0; v < 4; v++) acc[i][j][v] = 0.0f;

    // ---- prologue: STAGES-1 stages in flight ----
    load_stage(0, 0);
    load_stage(1, 1);

    for (int kt = 0; kt < KT; ++kt) {
        CP_WAIT1();
        __syncthreads();
        if (kt + STAGES - 1 < KT) load_stage((kt + STAGES - 1) % STAGES, kt + STAGES - 1);

        const uint32_t ab = sbase + (uint32_t)((kt % STAGES)) * STAGEB;
        const uint32_t bb = ab + ABYTES;

        #pragma unroll
        for (int h = 0; h < 2; h++) {
            const int slot16 = ((4 * h + t4) ^ sg) << 4;
            // B fragments: 4 n-tiles, each float4 = {b0(q0), b1(q0), b0(q1), b1(q1)}
            uint32_t bv[4][4];
            #pragma unroll
            for (int nt = 0; nt < 4; nt++) {
                const int n = wn * 32 + nt * 8 + g;
                LDS128(bv[nt][0], bv[nt][1], bv[nt][2], bv[nt][3],
                       bb + (uint32_t)(n * 128 + slot16));
            }
            #pragma unroll
            for (int mt = 0; mt < 4; mt++) {
                const int m = wm * 64 + mt * 16 + g;
                uint32_t r0[4], r1[4];
                LDS128(r0[0], r0[1], r0[2], r0[3], ab + (uint32_t)(m * 128 + slot16));
                LDS128(r1[0], r1[1], r1[2], r1[3], ab + (uint32_t)((m + 8) * 128 + slot16));
                #pragma unroll
                for (int nt = 0; nt < 4; nt++) {
                    mma_tf32(acc[mt][nt], r0[0], r1[0], r0[1], r1[1], bv[nt][0], bv[nt][1]);
                    mma_tf32(acc[mt][nt], r0[2], r1[2], r0[3], r1[3], bv[nt][2], bv[nt][3]);
                }
            }
        }
    }
    CP_WAIT0();

    // ---- epilogue ----
    #pragma unroll
    for (int mt = 0; mt < 4; mt++) {
        const int row = rowAb + wm * 64 + mt * 16 + g;
        #pragma unroll
        for (int nt = 0; nt < 4; nt++) {
            const int col = rowBb + wn * 32 + nt * 8 + t4 * 2;
            float b0 = 0.0f, b1 = 0.0f;
            if (bias) { b0 = __ldg(bias + col); b1 = __ldg(bias + col + 1); }
            float2 v0, v1;
            v0.x = acc[mt][nt][0] + b0; v0.y = acc[mt][nt][1] + b1;
            v1.x = acc[mt][nt][2] + b0; v1.y = acc[mt][nt][3] + b1;
            *reinterpret_cast<float2*>(C + (size_t)row * ldc + col) = v0;
            *reinterpret_cast<float2*>(C + (size_t)(row + 8) * ldc + col) = v1;
        }
    }
}

// ============================================================================
// Prepass kernels
// ============================================================================
// dst[i] = rna(src[kperm(i)])  (involution -> consistent permuted layout)
__global__ void round_perm(float* __restrict__ dst, const float* __restrict__ src, int n)
{
    int i = blockIdx.x * blockDim.x + threadIdx.x;
    if (i >= n) return;
    dst[i] = rnaf(src[kperm(i)]);
}

// WS = [A (64 rows); router_w (16 rows); zeros], rounded + kperm'd
__global__ void pack_ws(float* __restrict__ WS, const float* __restrict__ A,
                        const float* __restrict__ RW)
{
    int i = blockIdx.x * blockDim.x + threadIdx.x;
    if (i >= 128 * K_IN) return;
    int row = i >> 12;
    int col = kperm(i & 4095);
    float v = 0.0f;
    if (row < 64) v = A[row * K_IN + col];
    else if (row < 80) v = RW[(row - 64) * K_IN + col];
    WS[i] = rnaf(v);
}

// W2B[o][c] = rna(0.5 * B[e,o,r]) with (e,r) from kperm'd column c
__global__ void pack_w2b(float* __restrict__ W2B, const float* __restrict__ B)
{
    int i = blockIdx.x * blockDim.x + threadIdx.x;
    if (i >= N_OUT * K_LORA) return;
    int o = i >> 10;
    int c0 = kperm(i & 1023);
    int e = c0 >> 6;
    int r = c0 & 63;
    W2B[i] = rnaf(0.5f * B[((size_t)e << 18) + ((size_t)o << 6) + r]);
}

// ============================================================================
// Routing: one warp per token; writes U row rounded + kperm'd.
// ============================================================================
__global__ void routing_kernel(float* __restrict__ U, const float* __restrict__ HL)
{
    const int wid = (blockIdx.x * blockDim.x + threadIdx.x) >> 5;
    const int lane = threadIdx.x & 31;
    if (wid >= M_TOK) return;

    const float* hl = HL + (size_t)wid * 128;

    float logit = (lane < NEXP) ? hl[64 + lane] : -1e30f;
    float mx = logit;
    #pragma unroll
    for (int o = 16; o > 0; o >>= 1) mx = fmaxf(mx, __shfl_xor_sync(0xffffffffu, mx, o));
    float p = (lane < NEXP) ? __expf(logit - mx) : 0.0f;
    float s = p;
    #pragma unroll
    for (int o = 16; o > 0; o >>= 1) s += __shfl_xor_sync(0xffffffffu, s, o);
    const float prob = p / s;

    float v1 = prob; int i1 = (lane < NEXP) ? lane : 1000;
    #pragma unroll
    for (int o = 16; o > 0; o >>= 1) {
        float vo = __shfl_xor_sync(0xffffffffu, v1, o);
        int io = __shfl_xor_sync(0xffffffffu, i1, o);
        if (vo > v1 || (vo == v1 && io < i1)) { v1 = vo; i1 = io; }
    }
    float v2 = (lane == i1) ? -1.0f : prob;
    int i2 = (lane < NEXP && lane != i1) ? lane : 1000;
    #pragma unroll
    for (int o = 16; o > 0; o >>= 1) {
        float vo = __shfl_xor_sync(0xffffffffu, v2, o);
        int io = __shfl_xor_sync(0xffffffffu, i2, o);
        if (vo > v2 || (vo == v2 && io < i2)) { v2 = vo; i2 = io; }
    }

    const float rn = 1.0f / (v1 + v2 + 1e-6f);
    const float w1 = v1 * rn;
    const float w2 = v2 * rn;

    const float h0 = hl[lane];
    const float h1 = hl[lane + 32];

    float* urow = U + (size_t)wid * K_LORA;
    #pragma unroll
    for (int j = 0; j < 32; j++) {
        const int e = j >> 1;
        const float w = (e == i1) ? w1 : ((e == i2) ? w2 : 0.0f);
        const float hv = (j & 1) ? h1 : h0;
        const int c = j * 32 + lane;
        const int dst = (c & ~15) | ((lane & 3) << 2) | ((lane >> 2) & 3);
        urow[dst] = rnaf(w * hv);
    }
}

// ============================================================================
// Launch
// ============================================================================
extern "C" void kernel_launch(void* const* d_in, const int* in_sizes, int n_in,
                              void* d_out, int out_size)
{
    const float* x      = (const float*)d_in[0];
    const float* base_w = (const float*)d_in[1];
    const float* base_b = (const float*)d_in[2];
    const float* A      = (const float*)d_in[3];
    const float* B      = (const float*)d_in[4];
    const float* rw     = (const float*)d_in[5];
    float* out = (float*)d_out;

    float *xr, *wr, *ws, *hl, *u, *w2b;
    cudaGetSymbolAddress((void**)&xr,  g_Xr);
    cudaGetSymbolAddress((void**)&wr,  g_Wr);
    cudaGetSymbolAddress((void**)&ws,  g_WS);
    cudaGetSymbolAddress((void**)&hl,  g_HL);
    cudaGetSymbolAddress((void**)&u,   g_U);
    cudaGetSymbolAddress((void**)&w2b, g_W2B);

    cudaFuncSetAttribute(gemm_tf32, cudaFuncAttributeMaxDynamicSharedMemorySize, SMEM_BYTES);

    // prepass: rounded + kperm'd operands
    {
        int nx = M_TOK * K_IN;
        round_perm<<<(nx + 511) / 512, 512>>>(xr, x, nx);
        int nw = N_OUT * K_IN;
        round_perm<<<(nw + 511) / 512, 512>>>(wr, base_w, nw);
    }
    pack_ws <<<(128 * K_IN + 255) / 256, 256>>>(ws, A, rw);
    pack_w2b<<<(N_OUT * K_LORA + 255) / 256, 256>>>(w2b, B);

    // HL = Xr @ WS^T   (N=128, K=4096)
    {
        dim3 grid(1, M_TOK / BM);
        gemm_tf32<<<grid, NTH, SMEM_BYTES>>>(
            xr, ws, K_IN, K_IN, K_IN / BK,
            nullptr, nullptr, 0, 0, 0,
            nullptr, hl, 128);
    }

    routing_kernel<<<M_TOK / 8, 256>>>(u, hl);

    // out = Xr @ Wr^T + U @ W2B^T + bias   (N=4096, K=4096+1024)
    {
        dim3 grid(N_OUT / BN, M_TOK / BM);
        gemm_tf32<<<grid, NTH, SMEM_BYTES>>>(
            xr, wr, K_IN, K_IN, K_IN / BK,
            u, w2b, K_LORA, K_LORA, K_LORA / BK,
            base_b, out, N_OUT);
    }
}

// round 6
// speedup vs baseline: 1.1816x; 1.0499x over previous
#include <cuda_runtime.h>
#include <cstdint>
#include <cstddef>

// ============================================================================
// ResMoELoRALinear, folded:
//   HL  = Xr @ WS^T                      (M=8192, N=128, K=4096)
//   U[t, e*64+r] = combine[t,e]*h[t,r]
//   out = Xr @ Wr^T + U @ W2B^T + bias   (M=8192, N=4096, K=4096+1024)
// All GEMM operands pre-rounded to tf32 (RNA) AND K-permuted within each
// aligned 16-block by p(k) = (k&3)*4 + (k>>2) (involution, both sides of every
// dot product -> results unchanged). Each mma fragment = contiguous float4.
// ============================================================================

#define M_TOK  8192
#define N_OUT  4096
#define K_IN   4096
#define K_LORA 1024
#define NEXP   16

#define BM     128
#define BN     128
#define BK     32
#define STAGES 3
#define NTH    128          // 4 warps, warp grid 2x2, warp tile 64x64

#define ABYTES (BM * BK * 4)          // 16384
#define BBYTES (BN * BK * 4)          // 16384
#define STAGEB (ABYTES + BBYTES)      // 32768
#define SMEM_BYTES (STAGES * STAGEB)  // 98304

// -------- scratch (device globals; no allocation allowed) --------
__device__ float g_Xr[(size_t)M_TOK * K_IN];
__device__ float g_Wr[(size_t)N_OUT * K_IN];
__device__ float g_WS[128 * K_IN];
__device__ float g_HL[M_TOK * 128];
__device__ float g_U[(size_t)M_TOK * K_LORA];
__device__ float g_W2B[(size_t)N_OUT * K_LORA];

// ---------------- helpers ----------------
__device__ __forceinline__ uint32_t smem_u32(const void* p) {
    uint32_t a;
    asm("{ .reg .u64 t; cvta.to.shared.u64 t, %1; cvt.u32.u64 %0, t; }" : "=r"(a) : "l"(p));
    return a;
}
__device__ __forceinline__ float rnaf(float f) {
    uint32_t u;
    asm("cvt.rna.tf32.f32 %0, %1;" : "=r"(u) : "f"(f));
    return __uint_as_float(u);
}
__device__ __forceinline__ int kperm(int i) {
    return (i & ~15) | ((i & 3) << 2) | ((i >> 2) & 3);
}

#define CP_ASYNC16(dst_u32, src_ptr) \
    asm volatile("cp.async.cg.shared.global [%0], [%1], 16;" :: "r"(dst_u32), "l"(src_ptr) : "memory")
#define CP_COMMIT() asm volatile("cp.async.commit_group;" ::: "memory")
#define CP_WAIT1()  asm volatile("cp.async.wait_group 1;" ::: "memory")
#define CP_WAIT0()  asm volatile("cp.async.wait_group 0;" ::: "memory")

#define LDS128(r0, r1, r2, r3, addr) \
    asm volatile("ld.shared.v4.b32 {%0,%1,%2,%3}, [%4];" \
        : "=r"(r0), "=r"(r1), "=r"(r2), "=r"(r3) : "r"(addr))

__device__ __forceinline__ void mma_tf32(float c[4],
                                         uint32_t a0, uint32_t a1, uint32_t a2, uint32_t a3,
                                         uint32_t b0, uint32_t b1) {
    asm volatile(
        "mma.sync.aligned.m16n8k8.row.col.f32.tf32.tf32.f32 "
        "{%0,%1,%2,%3}, {%4,%5,%6,%7}, {%8,%9}, {%0,%1,%2,%3};"
        : "+f"(c[0]), "+f"(c[1]), "+f"(c[2]), "+f"(c[3])
        : "r"(a0), "r"(a1), "r"(a2), "r"(a3), "r"(b0), "r"(b1));
}

// smem chunk swizzle: 16B chunk c of row r stored at slot c ^ sigma(r&7)
__device__ __forceinline__ int sigma(int g) { return ((g & 1) << 2) | (g >> 1); }

// ============================================================================
// Two-segment NT GEMM: C = A1@B1^T (kt1 k-tiles) + A2@B2^T (kt2) + bias
// 128 threads, warp grid 2(m) x 2(n), warp tile 64x64.
// ============================================================================
__global__ __launch_bounds__(NTH, 2)
void gemm_tf32(const float* __restrict__ A1, const float* __restrict__ B1,
               int lda1, int ldb1, int kt1,
               const float* __restrict__ A2, const float* __restrict__ B2,
               int lda2, int ldb2, int kt2,
               const float* __restrict__ bias,
               float* __restrict__ C, int ldc)
{
    extern __shared__ char smem[];
    const uint32_t sbase = smem_u32(smem);

    const int tid  = threadIdx.x;
    const int warp = tid >> 5;
    const int lane = tid & 31;
    const int wm = warp >> 1;          // 0..1  (64 rows)
    const int wn = warp & 1;           // 0..1  (64 cols)
    const int g  = lane >> 2;          // 0..7
    const int t4 = lane & 3;           // 0..3
    const int sg = sigma(g);

    const int rowAb = blockIdx.y * BM;
    const int rowBb = blockIdx.x * BN;
    const int KT = kt1 + kt2;

    // ---- stage loader: 2048 16B chunks / 128 threads = 16 each ----
    const int ldr  = tid >> 3;         // 0..15
    const int ldc4 = tid & 7;          // chunk 0..7
    auto load_stage = [&](int st, int kt) {
        const float *Ap, *Bp;
        int la, lb, kb;
        if (kt < kt1) { Ap = A1; Bp = B1; la = lda1; lb = ldb1; kb = kt * BK; }
        else          { Ap = A2; Bp = B2; la = lda2; lb = ldb2; kb = (kt - kt1) * BK; }
        const uint32_t ab = sbase + (uint32_t)st * STAGEB;
        const uint32_t bb = ab + ABYTES;
        #pragma unroll
        for (int i = 0; i < 8; i++) {
            const int r = ldr + i * 16;                       // 0..127
            const int slot = ldc4 ^ sigma(r & 7);
            const float* srcA = Ap + (size_t)(rowAb + r) * la + kb + ldc4 * 4;
            CP_ASYNC16(ab + (uint32_t)(r * 128 + slot * 16), srcA);
            const float* srcB = Bp + (size_t)(rowBb + r) * lb + kb + ldc4 * 4;
            CP_ASYNC16(bb + (uint32_t)(r * 128 + slot * 16), srcB);
        }
        CP_COMMIT();
    };

    float acc[4][8][4];
    #pragma unroll
    for (int i = 0; i < 4; i++)
        #pragma unroll
        for (int j = 0; j < 8; j++)
            #pragma unroll
            for (int v = 0; v < 4; v++) acc[i][j][v] = 0.0f;

    load_stage(0, 0);
    load_stage(1, 1);

    for (int kt = 0; kt < KT; ++kt) {
        CP_WAIT1();
        __syncthreads();
        if (kt + STAGES - 1 < KT) load_stage((kt + STAGES - 1) % STAGES, kt + STAGES - 1);

        const uint32_t ab = sbase + (uint32_t)(kt % STAGES) * STAGEB;
        const uint32_t bb = ab + ABYTES;

        #pragma unroll
        for (int h = 0; h < 2; h++) {
            const int slot16 = ((4 * h + t4) ^ sg) << 4;
            // B fragments: 8 n-tiles, each float4 = {b(q0)k0-3 pair layout}
            uint32_t bv[8][4];
            #pragma unroll
            for (int nt = 0; nt < 8; nt++) {
                const int n = wn * 64 + nt * 8 + g;
                LDS128(bv[nt][0], bv[nt][1], bv[nt][2], bv[nt][3],
                       bb + (uint32_t)(n * 128 + slot16));
            }
            #pragma unroll
            for (int mt = 0; mt < 4; mt++) {
                const int m = wm * 64 + mt * 16 + g;
                uint32_t r0[4], r1[4];
                LDS128(r0[0], r0[1], r0[2], r0[3], ab + (uint32_t)(m * 128 + slot16));
                LDS128(r1[0], r1[1], r1[2], r1[3], ab + (uint32_t)((m + 8) * 128 + slot16));
                #pragma unroll
                for (int nt = 0; nt < 8; nt++) {
                    mma_tf32(acc[mt][nt], r0[0], r1[0], r0[1], r1[1], bv[nt][0], bv[nt][1]);
                    mma_tf32(acc[mt][nt], r0[2], r1[2], r0[3], r1[3], bv[nt][2], bv[nt][3]);
                }
            }
        }
    }
    CP_WAIT0();

    // ---- epilogue ----
    #pragma unroll
    for (int mt = 0; mt < 4; mt++) {
        const int row = rowAb + wm * 64 + mt * 16 + g;
        #pragma unroll
        for (int nt = 0; nt < 8; nt++) {
            const int col = rowBb + wn * 64 + nt * 8 + t4 * 2;
            float b0 = 0.0f, b1 = 0.0f;
            if (bias) { b0 = __ldg(bias + col); b1 = __ldg(bias + col + 1); }
            float2 v0, v1;
            v0.x = acc[mt][nt][0] + b0; v0.y = acc[mt][nt][1] + b1;
            v1.x = acc[mt][nt][2] + b0; v1.y = acc[mt][nt][3] + b1;
            *reinterpret_cast<float2*>(C + (size_t)row * ldc + col) = v0;
            *reinterpret_cast<float2*>(C + (size_t)(row + 8) * ldc + col) = v1;
        }
    }
}

// ============================================================================
// Prepass kernels
// ============================================================================
__global__ void round_perm(float* __restrict__ dst, const float* __restrict__ src, int n)
{
    int i = blockIdx.x * blockDim.x + threadIdx.x;
    if (i >= n) return;
    dst[i] = rnaf(src[kperm(i)]);
}

// Fused pack: WS (128*4096 elems) then W2B (4096*1024 elems)
__global__ void pack_fused(float* __restrict__ WS, float* __restrict__ W2B,
                           const float* __restrict__ A, const float* __restrict__ RW,
                           const float* __restrict__ B)
{
    int i = blockIdx.x * blockDim.x + threadIdx.x;
    const int NWS = 128 * K_IN;
    if (i < NWS) {
        int row = i >> 12;
        int col = kperm(i & 4095);
        float v = 0.0f;
        if (row < 64) v = A[row * K_IN + col];
        else if (row < 80) v = RW[(row - 64) * K_IN + col];
        WS[i] = rnaf(v);
    } else {
        int j = i - NWS;
        if (j >= N_OUT * K_LORA) return;
        int o = j >> 10;
        int c0 = kperm(j & 1023);
        int e = c0 >> 6;
        int r = c0 & 63;
        W2B[j] = rnaf(0.5f * B[((size_t)e << 18) + ((size_t)o << 6) + r]);
    }
}

// ============================================================================
// Routing: one warp per token; writes U row rounded + kperm'd.
// ============================================================================
__global__ void routing_kernel(float* __restrict__ U, const float* __restrict__ HL)
{
    const int wid = (blockIdx.x * blockDim.x + threadIdx.x) >> 5;
    const int lane = threadIdx.x & 31;
    if (wid >= M_TOK) return;

    const float* hl = HL + (size_t)wid * 128;

    float logit = (lane < NEXP) ? hl[64 + lane] : -1e30f;
    float mx = logit;
    #pragma unroll
    for (int o = 16; o > 0; o >>= 1) mx = fmaxf(mx, __shfl_xor_sync(0xffffffffu, mx, o));
    float p = (lane < NEXP) ? __expf(logit - mx) : 0.0f;
    float s = p;
    #pragma unroll
    for (int o = 16; o > 0; o >>= 1) s += __shfl_xor_sync(0xffffffffu, s, o);
    const float prob = p / s;

    float v1 = prob; int i1 = (lane < NEXP) ? lane : 1000;
    #pragma unroll
    for (int o = 16; o > 0; o >>= 1) {
        float vo = __shfl_xor_sync(0xffffffffu, v1, o);
        int io = __shfl_xor_sync(0xffffffffu, i1, o);
        if (vo > v1 || (vo == v1 && io < i1)) { v1 = vo; i1 = io; }
    }
    float v2 = (lane == i1) ? -1.0f : prob;
    int i2 = (lane < NEXP && lane != i1) ? lane : 1000;
    #pragma unroll
    for (int o = 16; o > 0; o >>= 1) {
        float vo = __shfl_xor_sync(0xffffffffu, v2, o);
        int io = __shfl_xor_sync(0xffffffffu, i2, o);
        if (vo > v2 || (vo == v2 && io < i2)) { v2 = vo; i2 = io; }
    }

    const float rn = 1.0f / (v1 + v2 + 1e-6f);
    const float w1 = v1 * rn;
    const float w2 = v2 * rn;

    const float h0 = hl[lane];
    const float h1 = hl[lane + 32];

    float* urow = U + (size_t)wid * K_LORA;
    #pragma unroll
    for (int j = 0; j < 32; j++) {
        const int e = j >> 1;
        const float w = (e == i1) ? w1 : ((e == i2) ? w2 : 0.0f);
        const float hv = (j & 1) ? h1 : h0;
        const int c = j * 32 + lane;
        const int dst = (c & ~15) | ((lane & 3) << 2) | ((lane >> 2) & 3);
        urow[dst] = rnaf(w * hv);
    }
}

// ============================================================================
// Launch (6 launches: main GEMM is #6 so ncu -s 5 -c 1 profiles it)
// ============================================================================
extern "C" void kernel_launch(void* const* d_in, const int* in_sizes, int n_in,
                              void* d_out, int out_size)
{
    const float* x      = (const float*)d_in[0];
    const float* base_w = (const float*)d_in[1];
    const float* base_b = (const float*)d_in[2];
    const float* A      = (const float*)d_in[3];
    const float* B      = (const float*)d_in[4];
    const float* rw     = (const float*)d_in[5];
    float* out = (float*)d_out;

    float *xr, *wr, *ws, *hl, *u, *w2b;
    cudaGetSymbolAddress((void**)&xr,  g_Xr);
    cudaGetSymbolAddress((void**)&wr,  g_Wr);
    cudaGetSymbolAddress((void**)&ws,  g_WS);
    cudaGetSymbolAddress((void**)&hl,  g_HL);
    cudaGetSymbolAddress((void**)&u,   g_U);
    cudaGetSymbolAddress((void**)&w2b, g_W2B);

    cudaFuncSetAttribute(gemm_tf32, cudaFuncAttributeMaxDynamicSharedMemorySize, SMEM_BYTES);

    // 1-2: rounded + kperm'd copies of x and base_w
    {
        int nx = M_TOK * K_IN;
        round_perm<<<(nx + 511) / 512, 512>>>(xr, x, nx);
        int nw = N_OUT * K_IN;
        round_perm<<<(nw + 511) / 512, 512>>>(wr, base_w, nw);
    }
    // 3: fused packs
    {
        int ntot = 128 * K_IN + N_OUT * K_LORA;
        pack_fused<<<(ntot + 255) / 256, 256>>>(ws, w2b, A, rw, B);
    }

    // 4: HL = Xr @ WS^T   (N=128, K=4096)
    {
        dim3 grid(1, M_TOK / BM);
        gemm_tf32<<<grid, NTH, SMEM_BYTES>>>(
            xr, ws, K_IN, K_IN, K_IN / BK,
            nullptr, nullptr, 0, 0, 0,
            nullptr, hl, 128);
    }

    // 5: routing + U build
    routing_kernel<<<M_TOK / 8, 256>>>(u, hl);

    // 6: out = Xr @ Wr^T + U @ W2B^T + bias   (N=4096, K=4096+1024)
    {
        dim3 grid(N_OUT / BN, M_TOK / BM);
        gemm_tf32<<<grid, NTH, SMEM_BYTES>>>(
            xr, wr, K_IN, K_IN, K_IN / BK,
            u, w2b, K_LORA, K_LORA, K_LORA / BK,
            base_b, out, N_OUT);
    }
}

// round 7
// speedup vs baseline: 1.9783x; 1.6743x over previous
#include <cuda_runtime.h>
#include <cuda_fp16.h>
#include <cstdint>
#include <cstddef>

// ============================================================================
// ResMoELoRALinear, folded, fp16-input / fp32-accum tensor path:
//   HL  = Xh @ WS^T                      (M=8192, N=128, K=4096)
//   U[t, e*64+r] = combine[t,e]*h[t,r]
//   out = Xh @ Wh^T + U @ W2B^T + bias   (M=8192, N=4096, K=4096+1024)
// fp16 has the same 11-bit significand as tf32 -> same rounding error as the
// passing tf32 version (rel_err 8.36e-4), but mma.m16n8k16.f16.f32 runs 2x.
// K indices are permuted within each aligned 32-block so each thread's
// m16n8k16 fragment for BOTH k16-halves is one contiguous 16B LDS128.
// Permutation applied to both operands of every dot product -> exact.
// ============================================================================

#define M_TOK  8192
#define N_OUT  4096
#define K_IN   4096
#define K_LORA 1024
#define NEXP   16

#define BN     128
#define BK     32
#define STAGES 4
#define NTH    128          // 4 warps, warp grid 2x2

// -------- scratch (device globals; no allocation allowed) --------
__device__ __half g_Xh[(size_t)M_TOK * K_IN];      // 64 MB
__device__ __half g_Wh[(size_t)N_OUT * K_IN];      // 32 MB
__device__ __half g_WS[128 * K_IN];                // 1 MB
__device__ float  g_HL[M_TOK * 128];               // 4 MB
__device__ __half g_U[(size_t)M_TOK * K_LORA];     // 16 MB
__device__ __half g_W2B[(size_t)N_OUT * K_LORA];   // 8 MB

// ---------------- helpers ----------------
__device__ __forceinline__ uint32_t smem_u32(const void* p) {
    uint32_t a;
    asm("{ .reg .u64 t; cvta.to.shared.u64 t, %1; cvt.u32.u64 %0, t; }" : "=r"(a) : "l"(p));
    return a;
}

// Within a 32-element K block, new slot s holds old element oldfn(s):
// thread t4 owns slots 8*t4..8*t4+7 = old {2t4,2t4+1,2t4+8,2t4+9,
//                                          16+2t4,16+2t4+1,16+2t4+8,16+2t4+9}
__device__ __forceinline__ int oldfn(int s) {
    int t4 = (s >> 3) & 3;
    int j  = s & 7;
    return 16 * ((j >> 2) & 1) + 2 * t4 + 8 * ((j >> 1) & 1) + (j & 1);
}

#define CP_ASYNC16(dst_u32, src_ptr) \
    asm volatile("cp.async.cg.shared.global [%0], [%1], 16;" :: "r"(dst_u32), "l"(src_ptr) : "memory")
#define CP_COMMIT() asm volatile("cp.async.commit_group;" ::: "memory")
#define CP_WAIT2()  asm volatile("cp.async.wait_group 2;" ::: "memory")
#define CP_WAIT0()  asm volatile("cp.async.wait_group 0;" ::: "memory")

#define LDS128(r0, r1, r2, r3, addr) \
    asm volatile("ld.shared.v4.b32 {%0,%1,%2,%3}, [%4];" \
        : "=r"(r0), "=r"(r1), "=r"(r2), "=r"(r3) : "r"(addr))

__device__ __forceinline__ void mma_f16(float c[4],
                                        uint32_t a0, uint32_t a1, uint32_t a2, uint32_t a3,
                                        uint32_t b0, uint32_t b1) {
    asm volatile(
        "mma.sync.aligned.m16n8k16.row.col.f32.f16.f16.f32 "
        "{%0,%1,%2,%3}, {%4,%5,%6,%7}, {%8,%9}, {%0,%1,%2,%3};"
        : "+f"(c[0]), "+f"(c[1]), "+f"(c[2]), "+f"(c[3])
        : "r"(a0), "r"(a1), "r"(a2), "r"(a3), "r"(b0), "r"(b1));
}

// ============================================================================
// Two-segment NT GEMM (fp16 in, fp32 out): C = A1@B1^T + A2@B2^T + bias
// Rows of A/B in smem: 64 bytes (32 fp16), 4x 16B chunks, chunk swizzle ^(r&3).
// Warp grid 2x2; warp tile (BMT/2) x 64.
// ============================================================================
template <int BMT>
__global__ __launch_bounds__(NTH, 2)
void gemm_f16(const __half* __restrict__ A1, const __half* __restrict__ B1,
              int lda1, int ldb1, int kt1,
              const __half* __restrict__ A2, const __half* __restrict__ B2,
              int lda2, int ldb2, int kt2,
              const float* __restrict__ bias,
              float* __restrict__ C, int ldc)
{
    constexpr int ABY = BMT * 64;
    constexpr int BBY = BN * 64;
    constexpr int STAGEB = ABY + BBY;
    constexpr int MT = BMT / 32;          // m-tiles per warp

    extern __shared__ char smem[];
    const uint32_t sbase = smem_u32(smem);

    const int tid  = threadIdx.x;
    const int warp = tid >> 5;
    const int lane = tid & 31;
    const int wm = warp >> 1;
    const int wn = warp & 1;
    const int g  = lane >> 2;
    const int t4 = lane & 3;

    const int rowAb = blockIdx.y * BMT;
    const int rowBb = blockIdx.x * BN;
    const int KT = kt1 + kt2;

    // ---- stage loader ----
    constexpr int TC = (BMT + BN) * 4;    // 16B chunks per stage
    auto load_stage = [&](int st, int kt) {
        const __half *Ap, *Bp;
        int la, lb, kb;
        if (kt < kt1) { Ap = A1; Bp = B1; la = lda1; lb = ldb1; kb = kt * BK; }
        else          { Ap = A2; Bp = B2; la = lda2; lb = ldb2; kb = (kt - kt1) * BK; }
        const uint32_t ab = sbase + (uint32_t)st * STAGEB;
        const uint32_t bb = ab + ABY;
        #pragma unroll
        for (int i = 0; i < TC / NTH; i++) {
            const int id = tid + i * NTH;
            const int r = id >> 2, c = id & 3;
            if (r < BMT) {
                const __half* src = Ap + (size_t)(rowAb + r) * la + kb + c * 8;
                CP_ASYNC16(ab + (uint32_t)(r * 64 + ((c ^ (r & 3)) << 4)), src);
            } else {
                const int rb = r - BMT;
                const __half* src = Bp + (size_t)(rowBb + rb) * lb + kb + c * 8;
                CP_ASYNC16(bb + (uint32_t)(rb * 64 + ((c ^ (rb & 3)) << 4)), src);
            }
        }
        CP_COMMIT();
    };

    float acc[MT][8][4];
    #pragma unroll
    for (int i = 0; i < MT; i++)
        #pragma unroll
        for (int j = 0; j < 8; j++)
            #pragma unroll
            for (int v = 0; v < 4; v++) acc[i][j][v] = 0.0f;

    load_stage(0, 0);
    load_stage(1, 1);
    load_stage(2, 2);

    for (int kt = 0; kt < KT; ++kt) {
        CP_WAIT2();
        __syncthreads();
        if (kt + STAGES - 1 < KT) load_stage((kt + STAGES - 1) & (STAGES - 1), kt + STAGES - 1);

        const uint32_t ab = sbase + (uint32_t)(kt & (STAGES - 1)) * STAGEB;
        const uint32_t bb = ab + ABY;

        // B fragments: one LDS128 per n-tile = both k16 halves
        uint32_t bv[8][4];
        #pragma unroll
        for (int nt = 0; nt < 8; nt++) {
            const int n = wn * 64 + nt * 8 + g;
            LDS128(bv[nt][0], bv[nt][1], bv[nt][2], bv[nt][3],
                   bb + (uint32_t)(n * 64 + ((t4 ^ (n & 3)) << 4)));
        }
        #pragma unroll
        for (int mt = 0; mt < MT; mt++) {
            const int m = wm * (BMT / 2) + mt * 16 + g;
            uint32_t r0[4], r1[4];
            LDS128(r0[0], r0[1], r0[2], r0[3],
                   ab + (uint32_t)(m * 64 + ((t4 ^ (m & 3)) << 4)));
            LDS128(r1[0], r1[1], r1[2], r1[3],
                   ab + (uint32_t)((m + 8) * 64 + ((t4 ^ ((m + 8) & 3)) << 4)));
            #pragma unroll
            for (int nt = 0; nt < 8; nt++) {
                mma_f16(acc[mt][nt], r0[0], r1[0], r0[1], r1[1], bv[nt][0], bv[nt][1]);
                mma_f16(acc[mt][nt], r0[2], r1[2], r0[3], r1[3], bv[nt][2], bv[nt][3]);
            }
        }
    }
    CP_WAIT0();

    // ---- epilogue ----
    #pragma unroll
    for (int mt = 0; mt < MT; mt++) {
        const int row = rowAb + wm * (BMT / 2) + mt * 16 + g;
        #pragma unroll
        for (int nt = 0; nt < 8; nt++) {
            const int col = rowBb + wn * 64 + nt * 8 + t4 * 2;
            float b0 = 0.0f, b1 = 0.0f;
            if (bias) { b0 = __ldg(bias + col); b1 = __ldg(bias + col + 1); }
            float2 v0, v1;
            v0.x = acc[mt][nt][0] + b0; v0.y = acc[mt][nt][1] + b1;
            v1.x = acc[mt][nt][2] + b0; v1.y = acc[mt][nt][3] + b1;
            *reinterpret_cast<float2*>(C + (size_t)row * ldc + col) = v0;
            *reinterpret_cast<float2*>(C + (size_t)(row + 8) * ldc + col) = v1;
        }
    }
}

// ============================================================================
// Prepass: fp32 -> fp16 (RN) with K permutation within 32-blocks
// ============================================================================
__global__ void cvt_perm(__half* __restrict__ dst, const float* __restrict__ src, int n)
{
    int i = blockIdx.x * blockDim.x + threadIdx.x;
    if (i >= n) return;
    int old = (i & ~31) | oldfn(i & 31);
    dst[i] = __float2half_rn(src[old]);
}

// Fused pack: WS (128*4096) then W2B (4096*1024), both fp16 + permuted
__global__ void pack_fused(__half* __restrict__ WS, __half* __restrict__ W2B,
                           const float* __restrict__ A, const float* __restrict__ RW,
                           const float* __restrict__ B)
{
    int i = blockIdx.x * blockDim.x + threadIdx.x;
    const int NWS = 128 * K_IN;
    if (i < NWS) {
        int row = i >> 12;
        int d = i & 4095;
        int col = (d & ~31) | oldfn(d & 31);
        float v = 0.0f;
        if (row < 64) v = A[row * K_IN + col];
        else if (row < 80) v = RW[(row - 64) * K_IN + col];
        WS[i] = __float2half_rn(v);
    } else {
        int j = i - NWS;
        if (j >= N_OUT * K_LORA) return;
        int o = j >> 10;
        int d = j & 1023;
        int c0 = (d & ~31) | oldfn(d & 31);
        int e = c0 >> 6;
        int r = c0 & 63;
        W2B[j] = __float2half_rn(0.5f * B[((size_t)e << 18) + ((size_t)o << 6) + r]);
    }
}

// ============================================================================
// Routing: one warp per token; writes U row fp16, K-permuted.
// Since 32 | (j*32), the permutation reduces to a per-lane index remap.
// ============================================================================
__global__ void routing_kernel(__half* __restrict__ U, const float* __restrict__ HL)
{
    const int wid = (blockIdx.x * blockDim.x + threadIdx.x) >> 5;
    const int lane = threadIdx.x & 31;
    if (wid >= M_TOK) return;

    const float* hl = HL + (size_t)wid * 128;

    float logit = (lane < NEXP) ? hl[64 + lane] : -1e30f;
    float mx = logit;
    #pragma unroll
    for (int o = 16; o > 0; o >>= 1) mx = fmaxf(mx, __shfl_xor_sync(0xffffffffu, mx, o));
    float p = (lane < NEXP) ? __expf(logit - mx) : 0.0f;
    float s = p;
    #pragma unroll
    for (int o = 16; o > 0; o >>= 1) s += __shfl_xor_sync(0xffffffffu, s, o);
    const float prob = p / s;

    float v1 = prob; int i1 = (lane < NEXP) ? lane : 1000;
    #pragma unroll
    for (int o = 16; o > 0; o >>= 1) {
        float vo = __shfl_xor_sync(0xffffffffu, v1, o);
        int io = __shfl_xor_sync(0xffffffffu, i1, o);
        if (vo > v1 || (vo == v1 && io < i1)) { v1 = vo; i1 = io; }
    }
    float v2 = (lane == i1) ? -1.0f : prob;
    int i2 = (lane < NEXP && lane != i1) ? lane : 1000;
    #pragma unroll
    for (int o = 16; o > 0; o >>= 1) {
        float vo = __shfl_xor_sync(0xffffffffu, v2, o);
        int io = __shfl_xor_sync(0xffffffffu, i2, o);
        if (vo > v2 || (vo == v2 && io < i2)) { v2 = vo; i2 = io; }
    }

    const float rn = 1.0f / (v1 + v2 + 1e-6f);
    const float w1 = v1 * rn;
    const float w2 = v2 * rn;

    const int q = oldfn(lane);          // permuted lane index (<32)
    const float h0 = hl[q];
    const float h1 = hl[q + 32];

    __half* urow = U + (size_t)wid * K_LORA;
    #pragma unroll
    for (int j = 0; j < 32; j++) {
        const int e = j >> 1;
        const float w = (e == i1) ? w1 : ((e == i2) ? w2 : 0.0f);
        const float hv = (j & 1) ? h1 : h0;
        urow[j * 32 + lane] = __float2half_rn(w * hv);
    }
}

// ============================================================================
// Launch (6 launches: main GEMM is #6 -> ncu -s 5 -c 1 profiles it)
// ============================================================================
#define SMEM_MAIN (STAGES * (128 + BN) * 64)   // 65536
#define SMEM_HL   (STAGES * (64  + BN) * 64)   // 49152

extern "C" void kernel_launch(void* const* d_in, const int* in_sizes, int n_in,
                              void* d_out, int out_size)
{
    const float* x      = (const float*)d_in[0];
    const float* base_w = (const float*)d_in[1];
    const float* base_b = (const float*)d_in[2];
    const float* A      = (const float*)d_in[3];
    const float* B      = (const float*)d_in[4];
    const float* rw     = (const float*)d_in[5];
    float* out = (float*)d_out;

    __half *xh, *wh, *ws, *u, *w2b;
    float *hl;
    cudaGetSymbolAddress((void**)&xh,  g_Xh);
    cudaGetSymbolAddress((void**)&wh,  g_Wh);
    cudaGetSymbolAddress((void**)&ws,  g_WS);
    cudaGetSymbolAddress((void**)&hl,  g_HL);
    cudaGetSymbolAddress((void**)&u,   g_U);
    cudaGetSymbolAddress((void**)&w2b, g_W2B);

    cudaFuncSetAttribute(gemm_f16<128>, cudaFuncAttributeMaxDynamicSharedMemorySize, SMEM_MAIN);
    cudaFuncSetAttribute(gemm_f16<64>,  cudaFuncAttributeMaxDynamicSharedMemorySize, SMEM_HL);

    // 1-2: fp16 + permuted copies of x and base_w
    {
        int nx = M_TOK * K_IN;
        cvt_perm<<<(nx + 511) / 512, 512>>>(xh, x, nx);
        int nw = N_OUT * K_IN;
        cvt_perm<<<(nw + 511) / 512, 512>>>(wh, base_w, nw);
    }
    // 3: fused packs
    {
        int ntot = 128 * K_IN + N_OUT * K_LORA;
        pack_fused<<<(ntot + 255) / 256, 256>>>(ws, w2b, A, rw, B);
    }

    // 4: HL = Xh @ WS^T   (N=128, K=4096), BM=64 -> 128 CTAs
    {
        dim3 grid(1, M_TOK / 64);
        gemm_f16<64><<<grid, NTH, SMEM_HL>>>(
            xh, ws, K_IN, K_IN, K_IN / BK,
            (const __half*)nullptr, (const __half*)nullptr, 0, 0, 0,
            nullptr, hl, 128);
    }

    // 5: routing + U build
    routing_kernel<<<M_TOK / 8, 256>>>(u, hl);

    // 6: out = Xh @ Wh^T + U @ W2B^T + bias   (N=4096, K=4096+1024)
    {
        dim3 grid(N_OUT / BN, M_TOK / 128);
        gemm_f16<128><<<grid, NTH, SMEM_MAIN>>>(
            xh, wh, K_IN, K_IN, K_IN / BK,
            u, w2b, K_LORA, K_LORA, K_LORA / BK,
            base_b, out, N_OUT);
    }
}

// round 9
// speedup vs baseline: 2.0563x; 1.0394x over previous
#include <cuda_runtime.h>
#include <cuda_fp16.h>
#include <cstdint>
#include <cstddef>

// ============================================================================
// ResMoELoRALinear, folded, fp16-input / fp32-accum tensor path:
//   HL  = Xh @ WS^T                      (M=8192, N=128, K=4096)
//   U[t, e*64+r] = combine[t,e]*h[t,r]
//   out = Xh @ Wh^T + U @ W2B^T + bias   (M=8192, N=4096, K=4096+1024)
// fp16 has the same 11-bit significand as tf32 -> same rounding statistics.
// K indices permuted within each aligned 32-block so each thread's m16n8k16
// fragment (both k16 halves) is one contiguous LDS128. Permutation applied to
// both operands of every dot product -> exact.
// Pipeline: 4-stage cp.async; EMPTY COMMIT each iteration with no load keeps
// the group count invariant so wait_group 2 always proves the stage complete
// (fixes round-8 tail race).
// ============================================================================

#define M_TOK  8192
#define N_OUT  4096
#define K_IN   4096
#define K_LORA 1024
#define NEXP   16

#define BK     32
#define STAGES 4
#define NTH    128          // 4 warps, warp grid 2x2

// -------- scratch (device globals; no allocation allowed) --------
__device__ __half g_Xh[(size_t)M_TOK * K_IN];      // 64 MB
__device__ __half g_Wh[(size_t)N_OUT * K_IN];      // 32 MB
__device__ __half g_WS[128 * K_IN];                // 1 MB
__device__ float  g_HL[M_TOK * 128];               // 4 MB
__device__ __half g_U[(size_t)M_TOK * K_LORA];     // 16 MB
__device__ __half g_W2B[(size_t)N_OUT * K_LORA];   // 8 MB

// ---------------- helpers ----------------
__device__ __forceinline__ uint32_t smem_u32(const void* p) {
    uint32_t a;
    asm("{ .reg .u64 t; cvta.to.shared.u64 t, %1; cvt.u32.u64 %0, t; }" : "=r"(a) : "l"(p));
    return a;
}

// Within a 32-element K block, new slot s holds old element oldfn(s).
__device__ __forceinline__ int oldfn(int s) {
    int t4 = (s >> 3) & 3;
    int j  = s & 7;
    return 16 * ((j >> 2) & 1) + 2 * t4 + 8 * ((j >> 1) & 1) + (j & 1);
}

#define CP_ASYNC16(dst_u32, src_ptr) \
    asm volatile("cp.async.cg.shared.global [%0], [%1], 16;" :: "r"(dst_u32), "l"(src_ptr) : "memory")
#define CP_COMMIT() asm volatile("cp.async.commit_group;" ::: "memory")
#define CP_WAIT2()  asm volatile("cp.async.wait_group 2;" ::: "memory")
#define CP_WAIT0()  asm volatile("cp.async.wait_group 0;" ::: "memory")

#define LDS128(r0, r1, r2, r3, addr) \
    asm volatile("ld.shared.v4.b32 {%0,%1,%2,%3}, [%4];" \
        : "=r"(r0), "=r"(r1), "=r"(r2), "=r"(r3) : "r"(addr))

__device__ __forceinline__ void mma_f16(float c[4],
                                        uint32_t a0, uint32_t a1, uint32_t a2, uint32_t a3,
                                        uint32_t b0, uint32_t b1) {
    asm volatile(
        "mma.sync.aligned.m16n8k16.row.col.f32.f16.f16.f32 "
        "{%0,%1,%2,%3}, {%4,%5,%6,%7}, {%8,%9}, {%0,%1,%2,%3};"
        : "+f"(c[0]), "+f"(c[1]), "+f"(c[2]), "+f"(c[3])
        : "r"(a0), "r"(a1), "r"(a2), "r"(a3), "r"(b0), "r"(b1));
}

// ============================================================================
// Two-segment NT GEMM (fp16 in, fp32 out): C = A1@B1^T + A2@B2^T + bias
// smem rows: 64 bytes (32 fp16) = 4x 16B chunks, chunk swizzle ^(r&3).
// 4 warps, warp grid 2x2; warp tile (BMT/2) x (BNT/2). Target 4 CTAs/SM.
// ============================================================================
template <int BMT, int BNT>
__global__ __launch_bounds__(NTH, 4)
void gemm_f16(const __half* __restrict__ A1, const __half* __restrict__ B1,
              int lda1, int ldb1, int kt1,
              const __half* __restrict__ A2, const __half* __restrict__ B2,
              int lda2, int ldb2, int kt2,
              const float* __restrict__ bias,
              float* __restrict__ C, int ldc)
{
    constexpr int ABY = BMT * 64;
    constexpr int BBY = BNT * 64;
    constexpr int STAGEB = ABY + BBY;
    constexpr int MT = BMT / 32;          // m-tiles per warp
    constexpr int NT = BNT / 16;          // n-tiles per warp (8 cols each)

    extern __shared__ char smem[];
    const uint32_t sbase = smem_u32(smem);

    const int tid  = threadIdx.x;
    const int warp = tid >> 5;
    const int lane = tid & 31;
    const int wm = warp >> 1;
    const int wn = warp & 1;
    const int g  = lane >> 2;
    const int t4 = lane & 3;

    const int rowAb = blockIdx.y * BMT;
    const int rowBb = blockIdx.x * BNT;
    const int KT = kt1 + kt2;

    // ---- stage loader ----
    constexpr int TC = (BMT + BNT) * 4;   // 16B chunks per stage
    auto load_stage = [&](int st, int kt) {
        const __half *Ap, *Bp;
        int la, lb, kb;
        if (kt < kt1) { Ap = A1; Bp = B1; la = lda1; lb = ldb1; kb = kt * BK; }
        else          { Ap = A2; Bp = B2; la = lda2; lb = ldb2; kb = (kt - kt1) * BK; }
        const uint32_t ab = sbase + (uint32_t)st * STAGEB;
        const uint32_t bb = ab + ABY;
        #pragma unroll
        for (int i = 0; i < TC / NTH; i++) {
            const int id = tid + i * NTH;
            const int r = id >> 2, c = id & 3;
            if (r < BMT) {
                const __half* src = Ap + (size_t)(rowAb + r) * la + kb + c * 8;
                CP_ASYNC16(ab + (uint32_t)(r * 64 + ((c ^ (r & 3)) << 4)), src);
            } else {
                const int rb = r - BMT;
                const __half* src = Bp + (size_t)(rowBb + rb) * lb + kb + c * 8;
                CP_ASYNC16(bb + (uint32_t)(rb * 64 + ((c ^ (rb & 3)) << 4)), src);
            }
        }
        CP_COMMIT();
    };

    float acc[MT][NT][4];
    #pragma unroll
    for (int i = 0; i < MT; i++)
        #pragma unroll
        for (int j = 0; j < NT; j++)
            #pragma unroll
            for (int v = 0; v < 4; v++) acc[i][j][v] = 0.0f;

    load_stage(0, 0);
    load_stage(1, 1);
    load_stage(2, 2);

    for (int kt = 0; kt < KT; ++kt) {
        CP_WAIT2();
        __syncthreads();
        // Keep group-count invariant: commit an (empty) group every iteration
        // so wait_group 2 always proves the consumed stage's group completed.
        if (kt + STAGES - 1 < KT) load_stage((kt + STAGES - 1) & (STAGES - 1), kt + STAGES - 1);
        else                      CP_COMMIT();

        const uint32_t ab = sbase + (uint32_t)(kt & (STAGES - 1)) * STAGEB;
        const uint32_t bb = ab + ABY;

        // B fragments: one LDS128 per n-tile = both k16 halves
        uint32_t bv[NT][4];
        #pragma unroll
        for (int nt = 0; nt < NT; nt++) {
            const int n = wn * (BNT / 2) + nt * 8 + g;
            LDS128(bv[nt][0], bv[nt][1], bv[nt][2], bv[nt][3],
                   bb + (uint32_t)(n * 64 + ((t4 ^ (n & 3)) << 4)));
        }
        #pragma unroll
        for (int mt = 0; mt < MT; mt++) {
            const int m = wm * (BMT / 2) + mt * 16 + g;
            uint32_t r0[4], r1[4];
            LDS128(r0[0], r0[1], r0[2], r0[3],
                   ab + (uint32_t)(m * 64 + ((t4 ^ (m & 3)) << 4)));
            LDS128(r1[0], r1[1], r1[2], r1[3],
                   ab + (uint32_t)((m + 8) * 64 + ((t4 ^ ((m + 8) & 3)) << 4)));
            #pragma unroll
            for (int nt = 0; nt < NT; nt++) {
                mma_f16(acc[mt][nt], r0[0], r1[0], r0[1], r1[1], bv[nt][0], bv[nt][1]);
                mma_f16(acc[mt][nt], r0[2], r1[2], r0[3], r1[3], bv[nt][2], bv[nt][3]);
            }
        }
    }
    CP_WAIT0();

    // ---- epilogue ----
    #pragma unroll
    for (int mt = 0; mt < MT; mt++) {
        const int row = rowAb + wm * (BMT / 2) + mt * 16 + g;
        #pragma unroll
        for (int nt = 0; nt < NT; nt++) {
            const int col = rowBb + wn * (BNT / 2) + nt * 8 + t4 * 2;
            float b0 = 0.0f, b1 = 0.0f;
            if (bias) { b0 = __ldg(bias + col); b1 = __ldg(bias + col + 1); }
            float2 v0, v1;
            v0.x = acc[mt][nt][0] + b0; v0.y = acc[mt][nt][1] + b1;
            v1.x = acc[mt][nt][2] + b0; v1.y = acc[mt][nt][3] + b1;
            *reinterpret_cast<float2*>(C + (size_t)row * ldc + col) = v0;
            *reinterpret_cast<float2*>(C + (size_t)(row + 8) * ldc + col) = v1;
        }
    }
}

// ============================================================================
// Prepass: fp32 -> fp16 (RN) with K permutation within 32-blocks
// ============================================================================
__global__ void cvt_perm(__half* __restrict__ dst, const float* __restrict__ src, int n)
{
    int i = blockIdx.x * blockDim.x + threadIdx.x;
    if (i >= n) return;
    int old = (i & ~31) | oldfn(i & 31);
    dst[i] = __float2half_rn(src[old]);
}

// Fused pack: WS (128*4096) then W2B (4096*1024), both fp16 + permuted
__global__ void pack_fused(__half* __restrict__ WS, __half* __restrict__ W2B,
                           const float* __restrict__ A, const float* __restrict__ RW,
                           const float* __restrict__ B)
{
    int i = blockIdx.x * blockDim.x + threadIdx.x;
    const int NWS = 128 * K_IN;
    if (i < NWS) {
        int row = i >> 12;
        int d = i & 4095;
        int col = (d & ~31) | oldfn(d & 31);
        float v = 0.0f;
        if (row < 64) v = A[row * K_IN + col];
        else if (row < 80) v = RW[(row - 64) * K_IN + col];
        WS[i] = __float2half_rn(v);
    } else {
        int j = i - NWS;
        if (j >= N_OUT * K_LORA) return;
        int o = j >> 10;
        int d = j & 1023;
        int c0 = (d & ~31) | oldfn(d & 31);
        int e = c0 >> 6;
        int r = c0 & 63;
        W2B[j] = __float2half_rn(0.5f * B[((size_t)e << 18) + ((size_t)o << 6) + r]);
    }
}

// ============================================================================
// Routing: one warp per token; writes U row fp16, K-permuted.
// ============================================================================
__global__ void routing_kernel(__half* __restrict__ U, const float* __restrict__ HL)
{
    const int wid = (blockIdx.x * blockDim.x + threadIdx.x) >> 5;
    const int lane = threadIdx.x & 31;
    if (wid >= M_TOK) return;

    const float* hl = HL + (size_t)wid * 128;

    float logit = (lane < NEXP) ? hl[64 + lane] : -1e30f;
    float mx = logit;
    #pragma unroll
    for (int o = 16; o > 0; o >>= 1) mx = fmaxf(mx, __shfl_xor_sync(0xffffffffu, mx, o));
    float p = (lane < NEXP) ? __expf(logit - mx) : 0.0f;
    float s = p;
    #pragma unroll
    for (int o = 16; o > 0; o >>= 1) s += __shfl_xor_sync(0xffffffffu, s, o);
    const float prob = p / s;

    float v1 = prob; int i1 = (lane < NEXP) ? lane : 1000;
    #pragma unroll
    for (int o = 16; o > 0; o >>= 1) {
        float vo = __shfl_xor_sync(0xffffffffu, v1, o);
        int io = __shfl_xor_sync(0xffffffffu, i1, o);
        if (vo > v1 || (vo == v1 && io < i1)) { v1 = vo; i1 = io; }
    }
    float v2 = (lane == i1) ? -1.0f : prob;
    int i2 = (lane < NEXP && lane != i1) ? lane : 1000;
    #pragma unroll
    for (int o = 16; o > 0; o >>= 1) {
        float vo = __shfl_xor_sync(0xffffffffu, v2, o);
        int io = __shfl_xor_sync(0xffffffffu, i2, o);
        if (vo > v2 || (vo == v2 && io < i2)) { v2 = vo; i2 = io; }
    }

    const float rn = 1.0f / (v1 + v2 + 1e-6f);
    const float w1 = v1 * rn;
    const float w2 = v2 * rn;

    const int q = oldfn(lane);          // permuted lane index (<32)
    const float h0 = hl[q];
    const float h1 = hl[q + 32];

    __half* urow = U + (size_t)wid * K_LORA;
    #pragma unroll
    for (int j = 0; j < 32; j++) {
        const int e = j >> 1;
        const float w = (e == i1) ? w1 : ((e == i2) ? w2 : 0.0f);
        const float hv = (j & 1) ? h1 : h0;
        urow[j * 32 + lane] = __float2half_rn(w * hv);
    }
}

// ============================================================================
// Launch (6 launches: main GEMM is #6 -> ncu -s 5 -c 1 profiles it)
// ============================================================================
#define SMEM_MAIN (STAGES * (128 + 64) * 64)   // 49152
#define SMEM_HL   (STAGES * (64 + 64) * 64)    // 32768

extern "C" void kernel_launch(void* const* d_in, const int* in_sizes, int n_in,
                              void* d_out, int out_size)
{
    const float* x      = (const float*)d_in[0];
    const float* base_w = (const float*)d_in[1];
    const float* base_b = (const float*)d_in[2];
    const float* A      = (const float*)d_in[3];
    const float* B      = (const float*)d_in[4];
    const float* rw     = (const float*)d_in[5];
    float* out = (float*)d_out;

    __half *xh, *wh, *ws, *u, *w2b;
    float *hl;
    cudaGetSymbolAddress((void**)&xh,  g_Xh);
    cudaGetSymbolAddress((void**)&wh,  g_Wh);
    cudaGetSymbolAddress((void**)&ws,  g_WS);
    cudaGetSymbolAddress((void**)&hl,  g_HL);
    cudaGetSymbolAddress((void**)&u,   g_U);
    cudaGetSymbolAddress((void**)&w2b, g_W2B);

    cudaFuncSetAttribute((void*)gemm_f16<128, 64>, cudaFuncAttributeMaxDynamicSharedMemorySize, SMEM_MAIN);
    cudaFuncSetAttribute((void*)gemm_f16<64, 64>,  cudaFuncAttributeMaxDynamicSharedMemorySize, SMEM_HL);

    // 1-2: fp16 + permuted copies of x and base_w
    {
        int nx = M_TOK * K_IN;
        cvt_perm<<<(nx + 511) / 512, 512>>>(xh, x, nx);
        int nw = N_OUT * K_IN;
        cvt_perm<<<(nw + 511) / 512, 512>>>(wh, base_w, nw);
    }
    // 3: fused packs
    {
        int ntot = 128 * K_IN + N_OUT * K_LORA;
        pack_fused<<<(ntot + 255) / 256, 256>>>(ws, w2b, A, rw, B);
    }

    // 4: HL = Xh @ WS^T   (N=128, K=4096): grid (2, 128) = 256 CTAs
    {
        dim3 grid(128 / 64, M_TOK / 64);
        gemm_f16<64, 64><<<grid, NTH, SMEM_HL>>>(
            xh, ws, K_IN, K_IN, K_IN / BK,
            (const __half*)nullptr, (const __half*)nullptr, 0, 0, 0,
            nullptr, hl, 128);
    }

    // 5: routing + U build
    routing_kernel<<<M_TOK / 8, 256>>>(u, hl);

    // 6: out = Xh @ Wh^T + U @ W2B^T + bias   (N=4096, K=4096+1024)
    {
        dim3 grid(N_OUT / 64, M_TOK / 128);
        gemm_f16<128, 64><<<grid, NTH, SMEM_MAIN>>>(
            xh, wh, K_IN, K_IN, K_IN / BK,
            u, w2b, K_LORA, K_LORA, K_LORA / BK,
            base_b, out, N_OUT);
    }
}